// round 4
// baseline (speedup 1.0000x reference)
#include <cuda_runtime.h>
#include <math.h>

#define BS   512
#define MM   8
#define TT   2048
#define NS   2047   // T-1 filter steps
#define DD   16
#define CH   8      // phase-2 chunk (steps staged in smem)

// Per-step affine-map matrices (shared across batches; ~4.7 MB total)
__device__ float g_M[NS * 256];   // M_t = F (I - K_t H)   [16][16]
__device__ float g_N[NS * 128];   // N_t = F K_t           [16][8]
__device__ float g_G[NS * 128];   // G_t = H M_t           [8][16]
__device__ float g_D[NS * 64];    // D_t = H N_t           [8][8]
__device__ int   g_tc;            // convergence step (steps >= g_tc are frozen copies)
__device__ unsigned char g_nan[BS];

// ---------------------------------------------------------------------------
// Kernel 0: per-batch NaN scan over x[:, :, 0..T-2]
// ---------------------------------------------------------------------------
__global__ void nan_scan_kernel(const float* __restrict__ x) {
    int b = blockIdx.x, tid = threadIdx.x;
    const float* xb = x + (size_t)b * MM * TT;
    int bad = 0;
    for (int idx = tid; idx < MM * TT; idx += 256) {
        int t = idx & (TT - 1);
        if (t < NS) {
            float v = xb[idx];
            bad |= isnan(v) ? 1 : 0;
        }
    }
    int any = __syncthreads_or(bad);
    if (tid == 0) g_nan[b] = any ? 1 : 0;
}

// ---------------------------------------------------------------------------
// Kernel 1: shared Riccati recursion -> M,N,G,D per step, with convergence exit
// Single block, 256 threads.
// ---------------------------------------------------------------------------
__global__ void phase1_kernel(const float* __restrict__ F_, const float* __restrict__ H_,
                              const float* __restrict__ Q_, const float* __restrict__ R_) {
    __shared__ float sF[256], sH[128], sQ[256], sR[64];
    __shared__ float cov[256], covn[256];
    __shared__ float P[128];        // cov H^T   [16][8]
    __shared__ float W[2][128];     // GJ workspace [8][16] (S | I)
    __shared__ float K[128];        // gain [16][8]
    __shared__ float CU[256];       // cov_u
    __shared__ float FC[256];       // F * sym(cov_u)
    __shared__ float Nn[128];       // F K
    __shared__ float Mm[256];       // F - (F K) H

    int tid = threadIdx.x;
    sF[tid] = F_[tid];
    sQ[tid] = Q_[tid];
    if (tid < 128) sH[tid] = H_[tid];
    if (tid < 64)  sR[tid] = R_[tid];
    cov[tid] = ((tid >> 4) == (tid & 15)) ? 1.f : 0.f;
    __syncthreads();

    int tc = NS;
    for (int t = 0; t < NS; t++) {
        // P = cov H^T
        if (tid < 128) {
            int i = tid >> 3, j = tid & 7;
            float s = 0.f;
            #pragma unroll
            for (int e = 0; e < 16; e++) s += cov[i * 16 + e] * sH[j * 16 + e];
            P[tid] = s;
        }
        __syncthreads();
        // W = [S | I],  S = H P + R
        if (tid < 128) {
            int a = tid >> 4, c = tid & 15;
            float v;
            if (c < 8) {
                float s = sR[a * 8 + c];
                #pragma unroll
                for (int e = 0; e < 16; e++) s += sH[a * 16 + e] * P[e * 8 + c];
                v = s;
            } else {
                v = (a == (c - 8)) ? 1.f : 0.f;
            }
            W[0][a * 16 + c] = v;
        }
        __syncthreads();
        // Gauss-Jordan (S is SPD -> no pivoting), ping-pong buffers
        #pragma unroll 1
        for (int k = 0; k < 8; k++) {
            int cur = k & 1;
            if (tid < 128) {
                int a = tid >> 4, c = tid & 15;
                float piv = W[cur][k * 16 + k];
                float wkc = W[cur][k * 16 + c] / piv;
                W[cur ^ 1][a * 16 + c] = (a == k) ? wkc
                                                  : W[cur][a * 16 + c] - W[cur][a * 16 + k] * wkc;
            }
            __syncthreads();
        }
        // K = P * Sinv  (Sinv = W[0][a][8+b])
        if (tid < 128) {
            int i = tid >> 3, j = tid & 7;
            float s = 0.f;
            #pragma unroll
            for (int a = 0; a < 8; a++) s += P[i * 8 + a] * W[0][a * 16 + 8 + j];
            K[tid] = s;
        }
        __syncthreads();
        // cov_u = cov - K P^T
        {
            int i = tid >> 4, j = tid & 15;
            float s = cov[tid];
            #pragma unroll
            for (int a = 0; a < 8; a++) s -= K[i * 8 + a] * P[j * 8 + a];
            CU[tid] = s;
        }
        __syncthreads();
        // FC = F * sym(cov_u);  N = F K
        {
            int i = tid >> 4, j = tid & 15;
            float s = 0.f;
            #pragma unroll
            for (int e = 0; e < 16; e++)
                s += sF[i * 16 + e] * 0.5f * (CU[e * 16 + j] + CU[j * 16 + e]);
            FC[tid] = s;
        }
        if (tid < 128) {
            int i = tid >> 3, a = tid & 7;
            float s = 0.f;
            #pragma unroll
            for (int e = 0; e < 16; e++) s += sF[i * 16 + e] * K[e * 8 + a];
            Nn[tid] = s;
        }
        __syncthreads();
        // covn = FC F^T + Q ;  M = F - N H
        {
            int i = tid >> 4, j = tid & 15;
            float s = sQ[tid];
            #pragma unroll
            for (int e = 0; e < 16; e++) s += FC[i * 16 + e] * sF[j * 16 + e];
            covn[tid] = s;
            float m = sF[tid];
            #pragma unroll
            for (int a = 0; a < 8; a++) m -= Nn[i * 8 + a] * sH[a * 16 + j];
            Mm[tid] = m;
        }
        __syncthreads();
        // G = H M ;  D = H N ;  store step matrices
        if (tid < 128) {
            int a = tid >> 4, j = tid & 15;
            float s = 0.f;
            #pragma unroll
            for (int e = 0; e < 16; e++) s += sH[a * 16 + e] * Mm[e * 16 + j];
            g_G[t * 128 + tid] = s;
        } else if (tid < 192) {
            int u = tid - 128, a = u >> 3, bcol = u & 7;
            float s = 0.f;
            #pragma unroll
            for (int e = 0; e < 16; e++) s += sH[a * 16 + e] * Nn[e * 8 + bcol];
            g_D[t * 64 + u] = s;
        }
        g_M[t * 256 + tid] = Mm[tid];
        if (tid < 128) g_N[t * 128 + tid] = Nn[tid];

        // convergence check (relative) and cov <- covn
        float dlt = fabsf(covn[tid] - cov[tid]);
        int big = dlt > 2e-5f * (fabsf(cov[tid]) + 1e-2f);
        int any = __syncthreads_or(big);
        cov[tid] = covn[tid];
        __syncthreads();
        if (!any) { tc = t + 1; break; }
    }
    if (tid == 0) g_tc = tc;
}

// ---------------------------------------------------------------------------
// Kernel 2: fill frozen tail [g_tc, NS) with step (g_tc - 1) matrices
// ---------------------------------------------------------------------------
__global__ void fill_kernel() {
    int t = blockIdx.x;
    int tc = g_tc;
    if (t < tc) return;
    int src = tc - 1;
    int tid = threadIdx.x;
    g_M[t * 256 + tid] = g_M[src * 256 + tid];
    if (tid < 128) {
        g_N[t * 128 + tid] = g_N[src * 128 + tid];
        g_G[t * 128 + tid] = g_G[src * 128 + tid];
    }
    if (tid < 64) g_D[t * 64 + tid] = g_D[src * 64 + tid];
}

// ---------------------------------------------------------------------------
// Kernel 3: per-batch mean recursion. 1 warp per batch, 8 warps per block
// sharing smem-staged chunks of M,N,G,D.
// Lanes 0..15: mean' = M mean + N obs
// Lanes 16..23: y     = G mean + D obs -> out
// Lanes 24..31: prefetch obs for t+1
// ---------------------------------------------------------------------------
__global__ void __launch_bounds__(256) phase2_kernel(const float* __restrict__ x,
                                                     float* __restrict__ out) {
    __shared__ __align__(16) float sM[CH][16][20];
    __shared__ __align__(16) float sN[CH][16][12];
    __shared__ __align__(16) float sG[CH][8][20];
    __shared__ __align__(16) float sD[CH][8][12];

    int tid = threadIdx.x;
    int w = tid >> 5, lane = tid & 31;
    int b = blockIdx.x * 8 + w;
    bool active = (g_nan[b] == 0);

    const float* xb = x + (size_t)b * MM * TT;
    float* ob = out + (size_t)b * MM * TT;

    float mean[16];
    #pragma unroll
    for (int i = 0; i < 16; i++) mean[i] = 0.f;
    if (active && lane < 8) ob[lane * TT + 0] = 0.f;

    float nextobs = 0.f;
    if (lane >= 24) nextobs = xb[(lane - 24) * TT + 0];
    float obs[8];

    int t = 0;
    for (int c0 = 0; c0 < NS; c0 += CH) {
        int nsteps = (NS - c0 < CH) ? (NS - c0) : CH;
        __syncthreads();
        // cooperative chunk load (coalesced LDG, padded STS)
        for (int idx = tid; idx < nsteps * 256; idx += 256) {
            int s = idx >> 8, r = (idx >> 4) & 15, cc = idx & 15;
            sM[s][r][cc] = g_M[(c0 + s) * 256 + (idx & 255)];
        }
        for (int idx = tid; idx < nsteps * 128; idx += 256) {
            int s = idx >> 7;
            int rn = (idx >> 3) & 15, cn = idx & 7;
            sN[s][rn][cn] = g_N[(c0 + s) * 128 + (idx & 127)];
            int rg = (idx >> 4) & 7, cg = idx & 15;
            sG[s][rg][cg] = g_G[(c0 + s) * 128 + (idx & 127)];
        }
        for (int idx = tid; idx < nsteps * 64; idx += 256) {
            int s = idx >> 6, r = (idx >> 3) & 7, cc = idx & 7;
            sD[s][r][cc] = g_D[(c0 + s) * 64 + (idx & 63)];
        }
        __syncthreads();

        if (active) {
            for (int s = 0; s < nsteps; s++, t++) {
                // broadcast obs_t from loader lanes
                #pragma unroll
                for (int j = 0; j < 8; j++)
                    obs[j] = __shfl_sync(0xffffffffu, nextobs, 24 + j);
                // prefetch obs_{t+1}
                if (lane >= 24 && (t + 1) < NS)
                    nextobs = xb[(lane - 24) * TT + (t + 1)];

                float nm = 0.f;
                if (lane < 16) {
                    const float4* Mr = (const float4*)&sM[s][lane][0];
                    float4 m0 = Mr[0], m1 = Mr[1], m2 = Mr[2], m3 = Mr[3];
                    const float4* Nr = (const float4*)&sN[s][lane][0];
                    float4 n0 = Nr[0], n1 = Nr[1];
                    float a0 = m0.x * mean[0] + m1.x * mean[4];
                    float a1 = m0.y * mean[1] + m1.y * mean[5];
                    float a2 = m0.z * mean[2] + m1.z * mean[6];
                    float a3 = m0.w * mean[3] + m1.w * mean[7];
                    a0 += m2.x * mean[8]  + m3.x * mean[12];
                    a1 += m2.y * mean[9]  + m3.y * mean[13];
                    a2 += m2.z * mean[10] + m3.z * mean[14];
                    a3 += m2.w * mean[11] + m3.w * mean[15];
                    a0 += n0.x * obs[0] + n1.x * obs[4];
                    a1 += n0.y * obs[1] + n1.y * obs[5];
                    a2 += n0.z * obs[2] + n1.z * obs[6];
                    a3 += n0.w * obs[3] + n1.w * obs[7];
                    nm = (a0 + a1) + (a2 + a3);
                } else if (lane < 24) {
                    int j = lane - 16;
                    const float4* Gr = (const float4*)&sG[s][j][0];
                    float4 g0 = Gr[0], g1 = Gr[1], g2 = Gr[2], g3 = Gr[3];
                    const float4* Dr = (const float4*)&sD[s][j][0];
                    float4 d0 = Dr[0], d1 = Dr[1];
                    float a0 = g0.x * mean[0] + g1.x * mean[4];
                    float a1 = g0.y * mean[1] + g1.y * mean[5];
                    float a2 = g0.z * mean[2] + g1.z * mean[6];
                    float a3 = g0.w * mean[3] + g1.w * mean[7];
                    a0 += g2.x * mean[8]  + g3.x * mean[12];
                    a1 += g2.y * mean[9]  + g3.y * mean[13];
                    a2 += g2.z * mean[10] + g3.z * mean[14];
                    a3 += g2.w * mean[11] + g3.w * mean[15];
                    a0 += d0.x * obs[0] + d1.x * obs[4];
                    a1 += d0.y * obs[1] + d1.y * obs[5];
                    a2 += d0.z * obs[2] + d1.z * obs[6];
                    a3 += d0.w * obs[3] + d1.w * obs[7];
                    ob[j * TT + t + 1] = (a0 + a1) + (a2 + a3);
                }
                // broadcast updated mean
                #pragma unroll
                for (int e = 0; e < 16; e++)
                    mean[e] = __shfl_sync(0xffffffffu, nm, e);
            }
        } else {
            t += nsteps;
        }
    }
}

// ---------------------------------------------------------------------------
// Kernel 4: fallback exact per-batch filter for NaN-containing batches
// (never runs for normal-distributed inputs; launched every call for
//  deterministic, capturable behavior)
// ---------------------------------------------------------------------------
__global__ void slow_kernel(const float* __restrict__ x, const float* __restrict__ F_,
                            const float* __restrict__ H_, const float* __restrict__ Q_,
                            const float* __restrict__ R_, float* __restrict__ out) {
    int b = blockIdx.x;
    if (!g_nan[b]) return;
    int tid = threadIdx.x;
    __shared__ float sF[256], sH[128], sQ[256], sR[64];
    __shared__ float cov[256], covn[256], P[128], W[2][128], K[128], CU[256], FC[256];
    __shared__ float mean[16], meanu[16], meanp[16], obs[8], resid[8];
    __shared__ int nanb;

    sF[tid] = F_[tid];
    sQ[tid] = Q_[tid];
    if (tid < 128) sH[tid] = H_[tid];
    if (tid < 64)  sR[tid] = R_[tid];
    cov[tid] = ((tid >> 4) == (tid & 15)) ? 1.f : 0.f;
    if (tid < 16) mean[tid] = 0.f;
    if (tid < 8)  out[((size_t)b * MM + tid) * TT] = 0.f;
    __syncthreads();

    for (int t = 0; t < NS; t++) {
        if (tid == 0) {
            int nb = 0;
            for (int j = 0; j < 8; j++) {
                float v = x[((size_t)b * MM + j) * TT + t];
                if (isnan(v)) { nb = 1; v = 0.f; }
                obs[j] = v;
            }
            nanb = nb;
        }
        __syncthreads();
        if (tid < 128) {
            int i = tid >> 3, j = tid & 7;
            float s = 0.f;
            #pragma unroll
            for (int e = 0; e < 16; e++) s += cov[i * 16 + e] * sH[j * 16 + e];
            P[tid] = s;
        }
        if (tid >= 128 && tid < 136) {
            int j = tid - 128;
            float s = obs[j];
            #pragma unroll
            for (int e = 0; e < 16; e++) s -= sH[j * 16 + e] * mean[e];
            resid[j] = s;
        }
        __syncthreads();
        if (tid < 128) {
            int a = tid >> 4, c = tid & 15;
            float v;
            if (c < 8) {
                float s = sR[a * 8 + c];
                #pragma unroll
                for (int e = 0; e < 16; e++) s += sH[a * 16 + e] * P[e * 8 + c];
                v = s;
            } else v = (a == (c - 8)) ? 1.f : 0.f;
            W[0][a * 16 + c] = v;
        }
        __syncthreads();
        #pragma unroll 1
        for (int k = 0; k < 8; k++) {
            int cur = k & 1;
            if (tid < 128) {
                int a = tid >> 4, c = tid & 15;
                float piv = W[cur][k * 16 + k];
                float wkc = W[cur][k * 16 + c] / piv;
                W[cur ^ 1][a * 16 + c] = (a == k) ? wkc
                                                  : W[cur][a * 16 + c] - W[cur][a * 16 + k] * wkc;
            }
            __syncthreads();
        }
        if (tid < 128) {
            int i = tid >> 3, j = tid & 7;
            float s = 0.f;
            #pragma unroll
            for (int a = 0; a < 8; a++) s += P[i * 8 + a] * W[0][a * 16 + 8 + j];
            K[tid] = s;
        }
        __syncthreads();
        if (tid < 16) {
            float s = mean[tid];
            #pragma unroll
            for (int a = 0; a < 8; a++) s += K[tid * 8 + a] * resid[a];
            meanu[tid] = nanb ? mean[tid] : s;
        }
        {
            int i = tid >> 4, j = tid & 15;
            float s = cov[tid];
            #pragma unroll
            for (int a = 0; a < 8; a++) s -= K[i * 8 + a] * P[j * 8 + a];
            CU[tid] = nanb ? cov[tid] : s;
        }
        __syncthreads();
        {
            int i = tid >> 4, j = tid & 15;
            float s = 0.f;
            #pragma unroll
            for (int e = 0; e < 16; e++)
                s += sF[i * 16 + e] * 0.5f * (CU[e * 16 + j] + CU[j * 16 + e]);
            FC[tid] = s;
        }
        if (tid < 16) {
            float s = 0.f;
            #pragma unroll
            for (int e = 0; e < 16; e++) s += sF[tid * 16 + e] * meanu[e];
            meanp[tid] = s;
        }
        __syncthreads();
        {
            int i = tid >> 4, j = tid & 15;
            float s = sQ[tid];
            #pragma unroll
            for (int e = 0; e < 16; e++) s += FC[i * 16 + e] * sF[j * 16 + e];
            covn[tid] = s;
        }
        if (tid < 8) {
            float s = 0.f;
            #pragma unroll
            for (int e = 0; e < 16; e++) s += sH[tid * 16 + e] * meanp[e];
            out[((size_t)b * MM + tid) * TT + t + 1] = s;
        }
        __syncthreads();
        cov[tid] = covn[tid];
        if (tid < 16) mean[tid] = meanp[tid];
        __syncthreads();
    }
}

// ---------------------------------------------------------------------------
extern "C" void kernel_launch(void* const* d_in, const int* in_sizes, int n_in,
                              void* d_out, int out_size) {
    const float* x = (const float*)d_in[0];
    const float* F = (const float*)d_in[1];
    const float* H = (const float*)d_in[2];
    const float* Q = (const float*)d_in[3];
    const float* R = (const float*)d_in[4];
    float* out = (float*)d_out;

    nan_scan_kernel<<<BS, 256>>>(x);
    phase1_kernel<<<1, 256>>>(F, H, Q, R);
    fill_kernel<<<NS, 256>>>();
    phase2_kernel<<<64, 256>>>(x, out);
    slow_kernel<<<BS, 256>>>(x, F, H, Q, R, out);
}

// round 5
// speedup vs baseline: 2.6518x; 2.6518x over previous
#include <cuda_runtime.h>
#include <math.h>

#define BS   512
#define MM   8
#define TT   2048
#define NS   2047   // T-1 filter steps
#define NCH  32     // time chunks
#define CL   64     // steps per chunk (last chunk = 63)
#define SUB  8      // phase-2b subchunk staged in smem

// Batch-independent per-step matrices
__device__ float g_M[NS * 256];   // M_t = F (I - K_t H)   [16][16]
__device__ float g_N[NS * 128];   // N_t = F K_t           [16][8]
__device__ float g_G[NS * 128];   // G_t = H M_t           [8][16]
__device__ float g_D[NS * 64];    // D_t = H N_t           [8][8]
// Packed combined maps: W1[t] = [M;G;0] (32x16), W2[t] = [N;D;0] (32x8)
__device__ float g_W1[(size_t)NS * 512];
__device__ float g_W2[(size_t)NS * 256];
// Chunk scan data
__device__ float g_P[NS * 128];        // P_t = Phi(chunk_end <- t+1) * N_t  [16][8]
__device__ float g_A[NCH * 256];       // A_c = prod of M over chunk         [16][16]
__device__ float g_b[BS * NCH * 16];   // per-batch chunk drive
__device__ float g_m0[BS * NCH * 16];  // per-batch chunk entry mean
__device__ int   g_tc;
__device__ unsigned char g_nan[BS];

// ---------------------------------------------------------------------------
// Kernel 0: per-batch NaN scan over x[:, :, 0..T-2]
// ---------------------------------------------------------------------------
__global__ void nan_scan_kernel(const float* __restrict__ x) {
    int b = blockIdx.x, tid = threadIdx.x;
    const float* xb = x + (size_t)b * MM * TT;
    int bad = 0;
    for (int idx = tid; idx < MM * TT; idx += 256) {
        int t = idx & (TT - 1);
        if (t < NS) {
            float v = xb[idx];
            bad |= isnan(v) ? 1 : 0;
        }
    }
    int any = __syncthreads_or(bad);
    if (tid == 0) g_nan[b] = any ? 1 : 0;
}

// ---------------------------------------------------------------------------
// Kernel 1: shared Riccati recursion -> M,N,G,D per step, convergence exit
// ---------------------------------------------------------------------------
__global__ void phase1_kernel(const float* __restrict__ F_, const float* __restrict__ H_,
                              const float* __restrict__ Q_, const float* __restrict__ R_) {
    __shared__ float sF[256], sH[128], sQ[256], sR[64];
    __shared__ float cov[256], covn[256];
    __shared__ float P[128];
    __shared__ float W[2][128];
    __shared__ float K[128];
    __shared__ float CU[256];
    __shared__ float FC[256];
    __shared__ float Nn[128];
    __shared__ float Mm[256];

    int tid = threadIdx.x;
    sF[tid] = F_[tid];
    sQ[tid] = Q_[tid];
    if (tid < 128) sH[tid] = H_[tid];
    if (tid < 64)  sR[tid] = R_[tid];
    cov[tid] = ((tid >> 4) == (tid & 15)) ? 1.f : 0.f;
    __syncthreads();

    int tc = NS;
    for (int t = 0; t < NS; t++) {
        if (tid < 128) {
            int i = tid >> 3, j = tid & 7;
            float s = 0.f;
            #pragma unroll
            for (int e = 0; e < 16; e++) s += cov[i * 16 + e] * sH[j * 16 + e];
            P[tid] = s;
        }
        __syncthreads();
        if (tid < 128) {
            int a = tid >> 4, c = tid & 15;
            float v;
            if (c < 8) {
                float s = sR[a * 8 + c];
                #pragma unroll
                for (int e = 0; e < 16; e++) s += sH[a * 16 + e] * P[e * 8 + c];
                v = s;
            } else {
                v = (a == (c - 8)) ? 1.f : 0.f;
            }
            W[0][a * 16 + c] = v;
        }
        __syncthreads();
        #pragma unroll 1
        for (int k = 0; k < 8; k++) {
            int cur = k & 1;
            if (tid < 128) {
                int a = tid >> 4, c = tid & 15;
                float piv = W[cur][k * 16 + k];
                float wkc = W[cur][k * 16 + c] / piv;
                W[cur ^ 1][a * 16 + c] = (a == k) ? wkc
                                                  : W[cur][a * 16 + c] - W[cur][a * 16 + k] * wkc;
            }
            __syncthreads();
        }
        if (tid < 128) {
            int i = tid >> 3, j = tid & 7;
            float s = 0.f;
            #pragma unroll
            for (int a = 0; a < 8; a++) s += P[i * 8 + a] * W[0][a * 16 + 8 + j];
            K[tid] = s;
        }
        __syncthreads();
        {
            int i = tid >> 4, j = tid & 15;
            float s = cov[tid];
            #pragma unroll
            for (int a = 0; a < 8; a++) s -= K[i * 8 + a] * P[j * 8 + a];
            CU[tid] = s;
        }
        __syncthreads();
        {
            int i = tid >> 4, j = tid & 15;
            float s = 0.f;
            #pragma unroll
            for (int e = 0; e < 16; e++)
                s += sF[i * 16 + e] * 0.5f * (CU[e * 16 + j] + CU[j * 16 + e]);
            FC[tid] = s;
        }
        if (tid < 128) {
            int i = tid >> 3, a = tid & 7;
            float s = 0.f;
            #pragma unroll
            for (int e = 0; e < 16; e++) s += sF[i * 16 + e] * K[e * 8 + a];
            Nn[tid] = s;
        }
        __syncthreads();
        {
            int i = tid >> 4, j = tid & 15;
            float s = sQ[tid];
            #pragma unroll
            for (int e = 0; e < 16; e++) s += FC[i * 16 + e] * sF[j * 16 + e];
            covn[tid] = s;
            float m = sF[tid];
            #pragma unroll
            for (int a = 0; a < 8; a++) m -= Nn[i * 8 + a] * sH[a * 16 + j];
            Mm[tid] = m;
        }
        __syncthreads();
        if (tid < 128) {
            int a = tid >> 4, j = tid & 15;
            float s = 0.f;
            #pragma unroll
            for (int e = 0; e < 16; e++) s += sH[a * 16 + e] * Mm[e * 16 + j];
            g_G[t * 128 + tid] = s;
        } else if (tid < 192) {
            int u = tid - 128, a = u >> 3, bcol = u & 7;
            float s = 0.f;
            #pragma unroll
            for (int e = 0; e < 16; e++) s += sH[a * 16 + e] * Nn[e * 8 + bcol];
            g_D[t * 64 + u] = s;
        }
        g_M[t * 256 + tid] = Mm[tid];
        if (tid < 128) g_N[t * 128 + tid] = Nn[tid];

        float dlt = fabsf(covn[tid] - cov[tid]);
        int big = dlt > 2e-5f * (fabsf(cov[tid]) + 1e-2f);
        int any = __syncthreads_or(big);
        cov[tid] = covn[tid];
        __syncthreads();
        if (!any) { tc = t + 1; break; }
    }
    if (tid == 0) g_tc = tc;
}

// ---------------------------------------------------------------------------
// Kernel 2: fill frozen tail [g_tc, NS) with step (g_tc - 1) matrices
// ---------------------------------------------------------------------------
__global__ void fill_kernel() {
    int t = blockIdx.x;
    int tc = g_tc;
    if (t < tc) return;
    int src = tc - 1;
    int tid = threadIdx.x;
    g_M[t * 256 + tid] = g_M[src * 256 + tid];
    if (tid < 128) {
        g_N[t * 128 + tid] = g_N[src * 128 + tid];
        g_G[t * 128 + tid] = g_G[src * 128 + tid];
    }
    if (tid < 64) g_D[t * 64 + tid] = g_D[src * 64 + tid];
}

// ---------------------------------------------------------------------------
// Kernel 2b: pack W1=[M;G;0] (32x16), W2=[N;D;0] (32x8)
// ---------------------------------------------------------------------------
__global__ void pack_kernel() {
    int t = blockIdx.x, tid = threadIdx.x;  // 512 threads
    {
        int r = tid >> 4, c = tid & 15;
        float v = 0.f;
        if (r < 16)       v = g_M[t * 256 + r * 16 + c];
        else if (r < 24)  v = g_G[t * 128 + (r - 16) * 16 + c];
        g_W1[(size_t)t * 512 + tid] = v;
    }
    if (tid < 256) {
        int r = tid >> 3, j = tid & 7;
        float v = 0.f;
        if (r < 16)       v = g_N[t * 128 + r * 8 + j];
        else if (r < 24)  v = g_D[t * 64 + (r - 16) * 8 + j];
        g_W2[(size_t)t * 256 + tid] = v;
    }
}

// ---------------------------------------------------------------------------
// Kernel 3: per-chunk suffix products -> A_c and P_t (batch-independent)
// One block per chunk, 256 threads.
// ---------------------------------------------------------------------------
__global__ void chunk_mats_kernel() {
    int c = blockIdx.x;
    int cstart = c * CL;
    int clen = (NS - cstart < CL) ? (NS - cstart) : CL;
    __shared__ float S[256], Mt[256], Nt[128];
    int tid = threadIdx.x;
    int i = tid >> 4, j = tid & 15;
    S[tid] = (i == j) ? 1.f : 0.f;

    int t = cstart + clen - 1;
    float mreg = g_M[t * 256 + tid];
    float nreg = (tid < 128) ? g_N[t * 128 + tid] : 0.f;
    __syncthreads();

    for (; t >= cstart; t--) {
        Mt[tid] = mreg;
        if (tid < 128) Nt[tid] = nreg;
        __syncthreads();
        if (t > cstart) {
            mreg = g_M[(t - 1) * 256 + tid];
            if (tid < 128) nreg = g_N[(t - 1) * 128 + tid];
        }
        // P_t = S * N_t   (S excludes step t here)
        if (tid < 128) {
            int i2 = tid >> 3, j2 = tid & 7;
            float s = 0.f;
            #pragma unroll
            for (int e = 0; e < 16; e++) s += S[i2 * 16 + e] * Nt[e * 8 + j2];
            g_P[t * 128 + tid] = s;
        }
        float sn = 0.f;
        #pragma unroll
        for (int e = 0; e < 16; e++) sn += S[i * 16 + e] * Mt[e * 16 + j];
        __syncthreads();
        S[tid] = sn;
        __syncthreads();
    }
    g_A[c * 256 + tid] = S[tid];
}

// ---------------------------------------------------------------------------
// Kernel 4: b_c = sum_t P_t * obs_t. Block = 1 chunk x 8 batches (8 warps).
// ---------------------------------------------------------------------------
#define BGB 8
__global__ void __launch_bounds__(256) bvec_kernel(const float* __restrict__ x) {
    int c = blockIdx.x & (NCH - 1);
    int bg = blockIdx.x >> 5;           // 64 batch groups
    int cstart = c * CL;
    int clen = (NS - cstart < CL) ? (NS - cstart) : CL;

    __shared__ __align__(16) float sP[CL * 128];       // [s][16][8]
    __shared__ __align__(16) float sX[BGB][CL][8];     // [b][s][m]
    int tid = threadIdx.x;

    for (int idx = tid; idx < clen * 128; idx += 256)
        sP[idx] = g_P[cstart * 128 + idx];
    for (int idx = tid; idx < BGB * 8 * clen; idx += 256) {
        int s = idx % clen;
        int bm = idx / clen;
        int m = bm & 7, b = bm >> 3;
        sX[b][s][m] = x[((size_t)(bg * BGB + b) * MM + m) * TT + cstart + s];
    }
    __syncthreads();

    int w = tid >> 5, lane = tid & 31;
    int b = bg * BGB + w;
    if (lane < 16) {
        float acc = 0.f;
        for (int s = 0; s < clen; s++) {
            const float4* pp = (const float4*)&sP[s * 128 + lane * 8];
            float4 p0 = pp[0], p1 = pp[1];
            const float4* op = (const float4*)&sX[w][s][0];
            float4 o0 = op[0], o1 = op[1];
            acc += p0.x * o0.x + p0.y * o0.y + p0.z * o0.z + p0.w * o0.w
                 + p1.x * o1.x + p1.y * o1.y + p1.z * o1.z + p1.w * o1.w;
        }
        g_b[(b * NCH + c) * 16 + lane] = acc;
    }
}

// ---------------------------------------------------------------------------
// Kernel 5: serial scan over 32 chunks -> entry mean m0 per (batch, chunk)
// 64 blocks x 256 threads (8 warps = 8 batches)
// ---------------------------------------------------------------------------
__global__ void __launch_bounds__(256) scan_kernel() {
    __shared__ float sA[NCH * 256];
    int tid = threadIdx.x;
    for (int idx = tid; idx < NCH * 256; idx += 256) sA[idx] = g_A[idx];
    __syncthreads();

    int w = tid >> 5, lane = tid & 31;
    int b = blockIdx.x * 8 + w;
    int row = lane & 15;

    float mean_i = 0.f;
    float breg = (lane < 16) ? g_b[(b * NCH + 0) * 16 + lane] : 0.f;
    for (int c = 0; c < NCH; c++) {
        if (lane < 16) g_m0[(b * NCH + c) * 16 + lane] = mean_i;
        float bn = (lane < 16 && c + 1 < NCH) ? g_b[(b * NCH + c + 1) * 16 + lane] : 0.f;
        float nm = breg;
        #pragma unroll
        for (int e = 0; e < 16; e++) {
            float me = __shfl_sync(0xffffffffu, mean_i, e);
            nm += sA[c * 256 + row * 16 + e] * me;
        }
        mean_i = nm;
        breg = bn;
    }
}

// ---------------------------------------------------------------------------
// Kernel 6: within-chunk recursion + output. Block = 1 chunk x 16 batches
// (16 warps, 512 threads). grid = 32 batchgroups x 32 chunks = 1024 blocks.
// Uniform lane work: row = lane of combined [M;G;0] / [N;D;0].
// ---------------------------------------------------------------------------
__global__ void __launch_bounds__(512) phase2b_kernel(const float* __restrict__ x,
                                                      float* __restrict__ out) {
    int c = blockIdx.x & (NCH - 1);
    int bg = blockIdx.x >> 5;           // 32 batch groups of 16
    int cstart = c * CL;
    int clen = (NS - cstart < CL) ? (NS - cstart) : CL;

    __shared__ __align__(16) float sW1[SUB][32][20];   // 20KB, stride 5 f4 (odd) -> conflict-free
    __shared__ __align__(16) float sW2[SUB][32][12];   // 12KB, stride 3 f4 (odd)
    __shared__ __align__(16) float sX[16][SUB][8];     // obs tile
    __shared__ __align__(16) float sY[16][8][SUB];     // y staging
    __shared__ __align__(16) float sMean[16][16];

    int tid = threadIdx.x, w = tid >> 5, lane = tid & 31;
    int b = bg * 16 + w;
    const size_t xbase = (size_t)b * MM * TT;

    if (lane < 16) sMean[w][lane] = g_m0[(b * NCH + c) * 16 + lane];
    if (c == 0 && lane < 8) out[xbase + (size_t)lane * TT] = 0.f;
    __syncwarp();

    for (int t0 = 0; t0 < clen; t0 += SUB) {
        int ns = (clen - t0 < SUB) ? (clen - t0) : SUB;
        __syncthreads();
        for (int idx = tid; idx < ns * 512; idx += 512) {
            int s = idx >> 9, rc = idx & 511;
            sW1[s][rc >> 4][rc & 15] = g_W1[(size_t)(cstart + t0 + s) * 512 + rc];
        }
        for (int idx = tid; idx < ns * 256; idx += 512) {
            int s = idx >> 8, rc = idx & 255;
            sW2[s][rc >> 3][rc & 7] = g_W2[(size_t)(cstart + t0 + s) * 256 + rc];
        }
        for (int idx = tid; idx < 16 * 8 * ns; idx += 512) {
            int s = idx % ns;
            int bm = idx / ns;
            int m = bm & 7, bb = bm >> 3;
            sX[bb][s][m] = x[((size_t)(bg * 16 + bb) * MM + m) * TT + cstart + t0 + s];
        }
        __syncthreads();

        for (int s = 0; s < ns; s++) {
            const float4* w1 = (const float4*)&sW1[s][lane][0];
            float4 a0 = w1[0], a1 = w1[1], a2 = w1[2], a3 = w1[3];
            const float4* w2 = (const float4*)&sW2[s][lane][0];
            float4 c0 = w2[0], c1 = w2[1];
            const float4* mp = (const float4*)&sMean[w][0];
            float4 m0 = mp[0], m1 = mp[1], m2 = mp[2], m3 = mp[3];
            const float4* op = (const float4*)&sX[w][s][0];
            float4 o0 = op[0], o1 = op[1];

            float s0 = a0.x * m0.x + a0.y * m0.y + a0.z * m0.z + a0.w * m0.w;
            float s1 = a1.x * m1.x + a1.y * m1.y + a1.z * m1.z + a1.w * m1.w;
            float s2 = a2.x * m2.x + a2.y * m2.y + a2.z * m2.z + a2.w * m2.w;
            float s3 = a3.x * m3.x + a3.y * m3.y + a3.z * m3.z + a3.w * m3.w;
            float s4 = c0.x * o0.x + c0.y * o0.y + c0.z * o0.z + c0.w * o0.w;
            float s5 = c1.x * o1.x + c1.y * o1.y + c1.z * o1.z + c1.w * o1.w;
            float acc = ((s0 + s1) + (s2 + s3)) + (s4 + s5);

            __syncwarp();
            if (lane < 16)      sMean[w][lane] = acc;
            else if (lane < 24) sY[w][lane - 16][s] = acc;
            __syncwarp();
        }
        __syncthreads();
        for (int idx = tid; idx < 16 * 8 * ns; idx += 512) {
            int s = idx % ns;
            int bm = idx / ns;
            int m = bm & 7, bb = bm >> 3;
            out[((size_t)(bg * 16 + bb) * MM + m) * TT + cstart + t0 + s + 1] = sY[bb][m][s];
        }
    }
}

// ---------------------------------------------------------------------------
// Kernel 7: exact per-batch fallback for NaN-containing batches
// ---------------------------------------------------------------------------
__global__ void slow_kernel(const float* __restrict__ x, const float* __restrict__ F_,
                            const float* __restrict__ H_, const float* __restrict__ Q_,
                            const float* __restrict__ R_, float* __restrict__ out) {
    int b = blockIdx.x;
    if (!g_nan[b]) return;
    int tid = threadIdx.x;
    __shared__ float sF[256], sH[128], sQ[256], sR[64];
    __shared__ float cov[256], covn[256], P[128], W[2][128], K[128], CU[256], FC[256];
    __shared__ float mean[16], meanu[16], meanp[16], obs[8], resid[8];
    __shared__ int nanb;

    sF[tid] = F_[tid];
    sQ[tid] = Q_[tid];
    if (tid < 128) sH[tid] = H_[tid];
    if (tid < 64)  sR[tid] = R_[tid];
    cov[tid] = ((tid >> 4) == (tid & 15)) ? 1.f : 0.f;
    if (tid < 16) mean[tid] = 0.f;
    if (tid < 8)  out[((size_t)b * MM + tid) * TT] = 0.f;
    __syncthreads();

    for (int t = 0; t < NS; t++) {
        if (tid == 0) {
            int nb = 0;
            for (int j = 0; j < 8; j++) {
                float v = x[((size_t)b * MM + j) * TT + t];
                if (isnan(v)) { nb = 1; v = 0.f; }
                obs[j] = v;
            }
            nanb = nb;
        }
        __syncthreads();
        if (tid < 128) {
            int i = tid >> 3, j = tid & 7;
            float s = 0.f;
            #pragma unroll
            for (int e = 0; e < 16; e++) s += cov[i * 16 + e] * sH[j * 16 + e];
            P[tid] = s;
        }
        if (tid >= 128 && tid < 136) {
            int j = tid - 128;
            float s = obs[j];
            #pragma unroll
            for (int e = 0; e < 16; e++) s -= sH[j * 16 + e] * mean[e];
            resid[j] = s;
        }
        __syncthreads();
        if (tid < 128) {
            int a = tid >> 4, c = tid & 15;
            float v;
            if (c < 8) {
                float s = sR[a * 8 + c];
                #pragma unroll
                for (int e = 0; e < 16; e++) s += sH[a * 16 + e] * P[e * 8 + c];
                v = s;
            } else v = (a == (c - 8)) ? 1.f : 0.f;
            W[0][a * 16 + c] = v;
        }
        __syncthreads();
        #pragma unroll 1
        for (int k = 0; k < 8; k++) {
            int cur = k & 1;
            if (tid < 128) {
                int a = tid >> 4, c = tid & 15;
                float piv = W[cur][k * 16 + k];
                float wkc = W[cur][k * 16 + c] / piv;
                W[cur ^ 1][a * 16 + c] = (a == k) ? wkc
                                                  : W[cur][a * 16 + c] - W[cur][a * 16 + k] * wkc;
            }
            __syncthreads();
        }
        if (tid < 128) {
            int i = tid >> 3, j = tid & 7;
            float s = 0.f;
            #pragma unroll
            for (int a = 0; a < 8; a++) s += P[i * 8 + a] * W[0][a * 16 + 8 + j];
            K[tid] = s;
        }
        __syncthreads();
        if (tid < 16) {
            float s = mean[tid];
            #pragma unroll
            for (int a = 0; a < 8; a++) s += K[tid * 8 + a] * resid[a];
            meanu[tid] = nanb ? mean[tid] : s;
        }
        {
            int i = tid >> 4, j = tid & 15;
            float s = cov[tid];
            #pragma unroll
            for (int a = 0; a < 8; a++) s -= K[i * 8 + a] * P[j * 8 + a];
            CU[tid] = nanb ? cov[tid] : s;
        }
        __syncthreads();
        {
            int i = tid >> 4, j = tid & 15;
            float s = 0.f;
            #pragma unroll
            for (int e = 0; e < 16; e++)
                s += sF[i * 16 + e] * 0.5f * (CU[e * 16 + j] + CU[j * 16 + e]);
            FC[tid] = s;
        }
        if (tid < 16) {
            float s = 0.f;
            #pragma unroll
            for (int e = 0; e < 16; e++) s += sF[tid * 16 + e] * meanu[e];
            meanp[tid] = s;
        }
        __syncthreads();
        {
            int i = tid >> 4, j = tid & 15;
            float s = sQ[tid];
            #pragma unroll
            for (int e = 0; e < 16; e++) s += FC[i * 16 + e] * sF[j * 16 + e];
            covn[tid] = s;
        }
        if (tid < 8) {
            float s = 0.f;
            #pragma unroll
            for (int e = 0; e < 16; e++) s += sH[tid * 16 + e] * meanp[e];
            out[((size_t)b * MM + tid) * TT + t + 1] = s;
        }
        __syncthreads();
        cov[tid] = covn[tid];
        if (tid < 16) mean[tid] = meanp[tid];
        __syncthreads();
    }
}

// ---------------------------------------------------------------------------
extern "C" void kernel_launch(void* const* d_in, const int* in_sizes, int n_in,
                              void* d_out, int out_size) {
    const float* x = (const float*)d_in[0];
    const float* F = (const float*)d_in[1];
    const float* H = (const float*)d_in[2];
    const float* Q = (const float*)d_in[3];
    const float* R = (const float*)d_in[4];
    float* out = (float*)d_out;

    nan_scan_kernel<<<BS, 256>>>(x);
    phase1_kernel<<<1, 256>>>(F, H, Q, R);
    fill_kernel<<<NS, 256>>>();
    pack_kernel<<<NS, 512>>>();
    chunk_mats_kernel<<<NCH, 256>>>();
    bvec_kernel<<<NCH * (BS / BGB), 256>>>(x);     // 32 chunks x 64 batchgroups
    scan_kernel<<<BS / 8, 256>>>();
    phase2b_kernel<<<NCH * (BS / 16), 512>>>(x, out); // 32 chunks x 32 batchgroups
    slow_kernel<<<BS, 256>>>(x, F, H, Q, R, out);
}

// round 7
// speedup vs baseline: 3.8467x; 1.4506x over previous
#include <cuda_runtime.h>
#include <math.h>

#define BS   512
#define MM   8
#define TT   2048
#define NS   2047   // T-1 filter steps
#define NCH  32     // time chunks
#define CL   64     // steps per chunk (last chunk = 63)
#define SUB  8      // phase-2b subchunk staged in smem
#define CONV_EPS 2.5e-4f

// Batch-independent per-step matrices
__device__ float g_M[NS * 256];   // M_t = F (I - K_t H)   [16][16]
__device__ float g_N[NS * 128];   // N_t = F K_t           [16][8]
// Packed combined maps: W1[t] = [M;G;0] (32x16), W2[t] = [N;D;0] (32x8)
// Rows 24-31 are NEVER written -> stay zero from static zero-init.
__device__ float g_W1[(size_t)NS * 512];
__device__ float g_W2[(size_t)NS * 256];
// Chunk scan data
__device__ float g_P[NS * 128];        // P_t = Phi(chunk_end <- t+1) * N_t  [16][8]
__device__ float g_A[NCH * 256];       // A_c = prod of M over chunk         [16][16]
__device__ float g_b[BS * NCH * 16];   // per-batch chunk drive
__device__ float g_m0[BS * NCH * 16];  // per-batch chunk entry mean
__device__ int   g_tc;
__device__ unsigned char g_nan[BS];

// ---------------------------------------------------------------------------
// Kernel 0: per-batch NaN scan over x[:, :, 0..T-2]
// ---------------------------------------------------------------------------
__global__ void nan_scan_kernel(const float* __restrict__ x) {
    int b = blockIdx.x, tid = threadIdx.x;
    const float* xb = x + (size_t)b * MM * TT;
    int bad = 0;
    for (int idx = tid; idx < MM * TT; idx += 256) {
        int t = idx & (TT - 1);
        if (t < NS) {
            float v = xb[idx];
            bad |= isnan(v) ? 1 : 0;
        }
    }
    int any = __syncthreads_or(bad);
    if (tid == 0) g_nan[b] = any ? 1 : 0;
}

// ---------------------------------------------------------------------------
// Kernel 1: shared Riccati recursion, barrier-light version.
// 256 threads, 6 barriers/step. Gauss-Jordan of the 8x8 innovation matrix
// runs entirely in warp 0's registers (shuffle-based) while other warps
// compute F*P, F*cov, (F*cov)*F^T in its shadow.
//   Nn  = (F P) Sinv              (= F K)
//   covn= F cov F^T + Q - 0.5*(Nn FP^T + FP Nn^T)
//   M   = F - Nn H ;  G = H M ;  D = H Nn
// ---------------------------------------------------------------------------
__global__ void __launch_bounds__(256) phase1_kernel(
        const float* __restrict__ F_, const float* __restrict__ H_,
        const float* __restrict__ Q_, const float* __restrict__ R_) {
    __shared__ float sF[256], sH[128], sQ[256], sR[64];
    __shared__ float cov[256];
    __shared__ float P[128];       // cov H^T           [16][8]
    __shared__ float W[128];       // [S | I]           [8][16]
    __shared__ float Sv[64];       // S^-1              [8][8]
    __shared__ float X[256];       // F cov             [16][16]
    __shared__ float Y[256];       // X F^T             [16][16]
    __shared__ float FP[128];      // F P               [16][8]
    __shared__ float Nn[128];      // FP Sinv           [16][8]
    __shared__ float Mm[256];      // F - Nn H
    __shared__ float covn[256];

    int tid = threadIdx.x;
    int i = tid >> 4, j = tid & 15;
    sF[tid] = F_[tid];
    sQ[tid] = Q_[tid];
    if (tid < 128) sH[tid] = H_[tid];
    if (tid < 64)  sR[tid] = R_[tid];
    cov[tid] = (i == j) ? 1.f : 0.f;
    __syncthreads();

    int tc = NS;
    for (int t = 0; t < NS; t++) {
        // ---- s0: P = cov H^T (tid<128) ; X rows 0-7 (tid>=128, cov symmetric)
        if (tid < 128) {
            int r = tid >> 3, c = tid & 7;
            float a0 = 0.f, a1 = 0.f;
            #pragma unroll
            for (int e = 0; e < 16; e += 2) {
                a0 += cov[r * 16 + e]     * sH[c * 16 + e];
                a1 += cov[r * 16 + e + 1] * sH[c * 16 + e + 1];
            }
            P[tid] = a0 + a1;
        } else {
            int u = tid - 128;               // rows 0-7 of X
            int r = u >> 4, c = u & 15;
            float a0 = 0.f, a1 = 0.f;
            #pragma unroll
            for (int e = 0; e < 16; e += 2) {
                a0 += sF[r * 16 + e]     * cov[c * 16 + e];
                a1 += sF[r * 16 + e + 1] * cov[c * 16 + e + 1];
            }
            X[u] = a0 + a1;
        }
        __syncthreads();
        // ---- s1: W=[S|I] (tid<128) ; X rows 8-15 (tid>=128)
        if (tid < 128) {
            int a = tid >> 4, c = tid & 15;
            float v;
            if (c < 8) {
                float s0 = sR[a * 8 + c], s1 = 0.f;
                #pragma unroll
                for (int e = 0; e < 16; e += 2) {
                    s0 += sH[a * 16 + e]     * P[e * 8 + c];
                    s1 += sH[a * 16 + e + 1] * P[(e + 1) * 8 + c];
                }
                v = s0 + s1;
            } else {
                v = (a == (c - 8)) ? 1.f : 0.f;
            }
            W[a * 16 + c] = v;
        } else {
            int r = tid >> 4, c = tid & 15;  // rows 8-15 of X
            float a0 = 0.f, a1 = 0.f;
            #pragma unroll
            for (int e = 0; e < 16; e += 2) {
                a0 += sF[r * 16 + e]     * cov[c * 16 + e];
                a1 += sF[r * 16 + e + 1] * cov[c * 16 + e + 1];
            }
            X[tid] = a0 + a1;
        }
        __syncthreads();
        // ---- s2: warp0 register GJ ; warps1-3 FP ; warps4-7 Y rows 0-7
        if (tid < 32) {
            int c = tid & 15, h = tid >> 4;
            float w[4];
            #pragma unroll
            for (int r = 0; r < 4; r++) w[r] = W[(h * 4 + r) * 16 + c];
            #pragma unroll
            for (int k = 0; k < 8; k++) {
                const int kh = k >> 2, kr = k & 3;
                float pivv  = __shfl_sync(0xffffffffu, w[kr], k + (kh << 4));
                float wkrow = __shfl_sync(0xffffffffu, w[kr], c + (kh << 4));
                float col0  = __shfl_sync(0xffffffffu, w[0], k + (h << 4));
                float col1  = __shfl_sync(0xffffffffu, w[1], k + (h << 4));
                float col2  = __shfl_sync(0xffffffffu, w[2], k + (h << 4));
                float col3  = __shfl_sync(0xffffffffu, w[3], k + (h << 4));
                float rp  = __fdividef(1.0f, pivv);
                float wkc = wkrow * rp;
                w[0] = (h * 4 + 0 == k) ? wkc : w[0] - col0 * wkc;
                w[1] = (h * 4 + 1 == k) ? wkc : w[1] - col1 * wkc;
                w[2] = (h * 4 + 2 == k) ? wkc : w[2] - col2 * wkc;
                w[3] = (h * 4 + 3 == k) ? wkc : w[3] - col3 * wkc;
            }
            if (c >= 8) {
                #pragma unroll
                for (int r = 0; r < 4; r++)
                    Sv[(h * 4 + r) * 8 + (c - 8)] = w[r];
            }
        } else if (tid < 128) {
            int u = tid - 32;                // FP: 128 elems over 96 threads
            {
                int r = u >> 3, c = u & 7;
                float a0 = 0.f, a1 = 0.f;
                #pragma unroll
                for (int e = 0; e < 16; e += 2) {
                    a0 += sF[r * 16 + e]     * P[e * 8 + c];
                    a1 += sF[r * 16 + e + 1] * P[(e + 1) * 8 + c];
                }
                FP[u] = a0 + a1;
            }
            if (u < 32) {
                int u2 = u + 96;
                int r = u2 >> 3, c = u2 & 7;
                float a0 = 0.f, a1 = 0.f;
                #pragma unroll
                for (int e = 0; e < 16; e += 2) {
                    a0 += sF[r * 16 + e]     * P[e * 8 + c];
                    a1 += sF[r * 16 + e + 1] * P[(e + 1) * 8 + c];
                }
                FP[u2] = a0 + a1;
            }
        } else {
            int u = tid - 128;               // Y rows 0-7
            int r = u >> 4, c = u & 15;
            float a0 = 0.f, a1 = 0.f;
            #pragma unroll
            for (int e = 0; e < 16; e += 2) {
                a0 += X[r * 16 + e]     * sF[c * 16 + e];
                a1 += X[r * 16 + e + 1] * sF[c * 16 + e + 1];
            }
            Y[u] = a0 + a1;
        }
        __syncthreads();
        // ---- s3: Nn = FP * Sinv (tid<128) ; Y rows 8-15 (tid>=128)
        if (tid < 128) {
            int r = tid >> 3, c = tid & 7;
            float s0 = 0.f, s1 = 0.f;
            #pragma unroll
            for (int a = 0; a < 8; a += 2) {
                s0 += FP[r * 8 + a]     * Sv[a * 8 + c];
                s1 += FP[r * 8 + a + 1] * Sv[(a + 1) * 8 + c];
            }
            Nn[tid] = s0 + s1;
        } else {
            int r = tid >> 4, c = tid & 15;  // rows 8-15 of Y
            float a0 = 0.f, a1 = 0.f;
            #pragma unroll
            for (int e = 0; e < 16; e += 2) {
                a0 += X[r * 16 + e]     * sF[c * 16 + e];
                a1 += X[r * 16 + e + 1] * sF[c * 16 + e + 1];
            }
            Y[tid] = a0 + a1;
        }
        __syncthreads();
        // ---- s4: covn and Mm (all 256)
        {
            float t1 = 0.f, t2 = 0.f, m = sF[tid];
            #pragma unroll
            for (int a = 0; a < 8; a++) {
                float ni = Nn[i * 8 + a], fi = FP[i * 8 + a];
                t1 += ni * FP[j * 8 + a];
                t2 += fi * Nn[j * 8 + a];
                m  -= ni * sH[a * 16 + j];
            }
            covn[tid] = Y[tid] + sQ[tid] - 0.5f * (t1 + t2);
            Mm[tid] = m;
        }
        __syncthreads();
        // ---- s5: outputs + convergence (syncthreads_or is the barrier)
        g_M[t * 256 + tid] = Mm[tid];
        g_W1[(size_t)t * 512 + tid] = Mm[tid];
        if (tid < 128) {
            g_N[t * 128 + tid] = Nn[tid];
            g_W2[(size_t)t * 256 + tid] = Nn[tid];
            int a = tid >> 4, jj = tid & 15;
            float s0 = 0.f, s1 = 0.f;
            #pragma unroll
            for (int e = 0; e < 16; e += 2) {
                s0 += sH[a * 16 + e]     * Mm[e * 16 + jj];
                s1 += sH[a * 16 + e + 1] * Mm[(e + 1) * 16 + jj];
            }
            g_W1[(size_t)t * 512 + 256 + tid] = s0 + s1;
        } else if (tid < 192) {
            int u = tid - 128, a = u >> 3, jj = u & 7;
            float s0 = 0.f, s1 = 0.f;
            #pragma unroll
            for (int e = 0; e < 16; e += 2) {
                s0 += sH[a * 16 + e]     * Nn[e * 8 + jj];
                s1 += sH[a * 16 + e + 1] * Nn[(e + 1) * 8 + jj];
            }
            g_W2[(size_t)t * 256 + 128 + u] = s0 + s1;
        }
        float oldc = cov[tid];
        float dlt = fabsf(covn[tid] - oldc);
        cov[tid] = covn[tid];
        int any = __syncthreads_or(dlt > CONV_EPS * (fabsf(oldc) + 1e-2f));
        if (!any) { tc = t + 1; break; }
    }
    if (tid == 0) g_tc = tc;
}

// ---------------------------------------------------------------------------
// Kernel 2: fill frozen tail [g_tc, NS) with step (g_tc - 1) matrices
// (g_W1 rows 24-31 / g_W2 rows 24-31 are always zero from static init.)
// ---------------------------------------------------------------------------
__global__ void fill_kernel() {
    int t = blockIdx.x;
    int tc = g_tc;
    if (t < tc) return;
    int src = tc - 1;
    int tid = threadIdx.x;
    g_M[t * 256 + tid] = g_M[src * 256 + tid];
    g_W1[(size_t)t * 512 + tid] = g_W1[(size_t)src * 512 + tid];
    if (tid < 128) {
        g_N[t * 128 + tid] = g_N[src * 128 + tid];
        g_W1[(size_t)t * 512 + 256 + tid] = g_W1[(size_t)src * 512 + 256 + tid];
        g_W2[(size_t)t * 256 + tid] = g_W2[(size_t)src * 256 + tid];
    }
    if (tid < 64)
        g_W2[(size_t)t * 256 + 128 + tid] = g_W2[(size_t)src * 256 + 128 + tid];
}

// ---------------------------------------------------------------------------
// Kernel 3: per-chunk suffix products -> A_c and P_t (batch-independent)
// ---------------------------------------------------------------------------
__global__ void chunk_mats_kernel() {
    int c = blockIdx.x;
    int cstart = c * CL;
    int clen = (NS - cstart < CL) ? (NS - cstart) : CL;
    __shared__ float S[256], Mt[256], Nt[128];
    int tid = threadIdx.x;
    int i = tid >> 4, j = tid & 15;
    S[tid] = (i == j) ? 1.f : 0.f;

    int t = cstart + clen - 1;
    float mreg = g_M[t * 256 + tid];
    float nreg = (tid < 128) ? g_N[t * 128 + tid] : 0.f;
    __syncthreads();

    for (; t >= cstart; t--) {
        Mt[tid] = mreg;
        if (tid < 128) Nt[tid] = nreg;
        __syncthreads();
        if (t > cstart) {
            mreg = g_M[(t - 1) * 256 + tid];
            if (tid < 128) nreg = g_N[(t - 1) * 128 + tid];
        }
        if (tid < 128) {
            int i2 = tid >> 3, j2 = tid & 7;
            float s = 0.f;
            #pragma unroll
            for (int e = 0; e < 16; e++) s += S[i2 * 16 + e] * Nt[e * 8 + j2];
            g_P[t * 128 + tid] = s;
        }
        float sn = 0.f;
        #pragma unroll
        for (int e = 0; e < 16; e++) sn += S[i * 16 + e] * Mt[e * 16 + j];
        __syncthreads();
        S[tid] = sn;
        __syncthreads();
    }
    g_A[c * 256 + tid] = S[tid];
}

// ---------------------------------------------------------------------------
// Kernel 4: b_c = sum_t P_t * obs_t. Block = 1 chunk x 8 batches (8 warps).
// ---------------------------------------------------------------------------
#define BGB 8
__global__ void __launch_bounds__(256) bvec_kernel(const float* __restrict__ x) {
    int c = blockIdx.x & (NCH - 1);
    int bg = blockIdx.x >> 5;           // 64 batch groups
    int cstart = c * CL;
    int clen = (NS - cstart < CL) ? (NS - cstart) : CL;

    __shared__ __align__(16) float sP[CL * 128];
    __shared__ __align__(16) float sX[BGB][CL][8];
    int tid = threadIdx.x;

    for (int idx = tid; idx < clen * 128; idx += 256)
        sP[idx] = g_P[cstart * 128 + idx];
    for (int idx = tid; idx < BGB * 8 * clen; idx += 256) {
        int s = idx % clen;
        int bm = idx / clen;
        int m = bm & 7, b = bm >> 3;
        sX[b][s][m] = x[((size_t)(bg * BGB + b) * MM + m) * TT + cstart + s];
    }
    __syncthreads();

    int w = tid >> 5, lane = tid & 31;
    int b = bg * BGB + w;
    if (lane < 16) {
        float acc = 0.f;
        for (int s = 0; s < clen; s++) {
            const float4* pp = (const float4*)&sP[s * 128 + lane * 8];
            float4 p0 = pp[0], p1 = pp[1];
            const float4* op = (const float4*)&sX[w][s][0];
            float4 o0 = op[0], o1 = op[1];
            acc += p0.x * o0.x + p0.y * o0.y + p0.z * o0.z + p0.w * o0.w
                 + p1.x * o1.x + p1.y * o1.y + p1.z * o1.z + p1.w * o1.w;
        }
        g_b[(b * NCH + c) * 16 + lane] = acc;
    }
}

// ---------------------------------------------------------------------------
// Kernel 5: serial scan over 32 chunks -> entry mean m0 per (batch, chunk)
// ---------------------------------------------------------------------------
__global__ void __launch_bounds__(256) scan_kernel() {
    __shared__ float sA[NCH * 256];
    int tid = threadIdx.x;
    for (int idx = tid; idx < NCH * 256; idx += 256) sA[idx] = g_A[idx];
    __syncthreads();

    int w = tid >> 5, lane = tid & 31;
    int b = blockIdx.x * 8 + w;
    int row = lane & 15;

    float mean_i = 0.f;
    float breg = (lane < 16) ? g_b[(b * NCH + 0) * 16 + lane] : 0.f;
    for (int c = 0; c < NCH; c++) {
        if (lane < 16) g_m0[(b * NCH + c) * 16 + lane] = mean_i;
        float bn = (lane < 16 && c + 1 < NCH) ? g_b[(b * NCH + c + 1) * 16 + lane] : 0.f;
        float nm = breg;
        #pragma unroll
        for (int e = 0; e < 16; e++) {
            float me = __shfl_sync(0xffffffffu, mean_i, e);
            nm += sA[c * 256 + row * 16 + e] * me;
        }
        mean_i = nm;
        breg = bn;
    }
}

// ---------------------------------------------------------------------------
// Kernel 6: within-chunk recursion + output. Block = 1 chunk x 16 batches.
// ---------------------------------------------------------------------------
__global__ void __launch_bounds__(512) phase2b_kernel(const float* __restrict__ x,
                                                      float* __restrict__ out) {
    int c = blockIdx.x & (NCH - 1);
    int bg = blockIdx.x >> 5;           // 32 batch groups of 16
    int cstart = c * CL;
    int clen = (NS - cstart < CL) ? (NS - cstart) : CL;

    __shared__ __align__(16) float sW1[SUB][32][20];
    __shared__ __align__(16) float sW2[SUB][32][12];
    __shared__ __align__(16) float sX[16][SUB][8];
    __shared__ __align__(16) float sY[16][8][SUB];
    __shared__ __align__(16) float sMean[16][16];

    int tid = threadIdx.x, w = tid >> 5, lane = tid & 31;
    int b = bg * 16 + w;
    const size_t xbase = (size_t)b * MM * TT;

    if (lane < 16) sMean[w][lane] = g_m0[(b * NCH + c) * 16 + lane];
    if (c == 0 && lane < 8) out[xbase + (size_t)lane * TT] = 0.f;
    __syncwarp();

    for (int t0 = 0; t0 < clen; t0 += SUB) {
        int ns = (clen - t0 < SUB) ? (clen - t0) : SUB;
        __syncthreads();
        for (int idx = tid; idx < ns * 512; idx += 512) {
            int s = idx >> 9, rc = idx & 511;
            sW1[s][rc >> 4][rc & 15] = g_W1[(size_t)(cstart + t0 + s) * 512 + rc];
        }
        for (int idx = tid; idx < ns * 256; idx += 512) {
            int s = idx >> 8, rc = idx & 255;
            sW2[s][rc >> 3][rc & 7] = g_W2[(size_t)(cstart + t0 + s) * 256 + rc];
        }
        for (int idx = tid; idx < 16 * 8 * ns; idx += 512) {
            int s = idx % ns;
            int bm = idx / ns;
            int m = bm & 7, bb = bm >> 3;
            sX[bb][s][m] = x[((size_t)(bg * 16 + bb) * MM + m) * TT + cstart + t0 + s];
        }
        __syncthreads();

        for (int s = 0; s < ns; s++) {
            const float4* w1 = (const float4*)&sW1[s][lane][0];
            float4 a0 = w1[0], a1 = w1[1], a2 = w1[2], a3 = w1[3];
            const float4* w2 = (const float4*)&sW2[s][lane][0];
            float4 c0 = w2[0], c1 = w2[1];
            const float4* mp = (const float4*)&sMean[w][0];
            float4 m0 = mp[0], m1 = mp[1], m2 = mp[2], m3 = mp[3];
            const float4* op = (const float4*)&sX[w][s][0];
            float4 o0 = op[0], o1 = op[1];

            float s0 = a0.x * m0.x + a0.y * m0.y + a0.z * m0.z + a0.w * m0.w;
            float s1 = a1.x * m1.x + a1.y * m1.y + a1.z * m1.z + a1.w * m1.w;
            float s2 = a2.x * m2.x + a2.y * m2.y + a2.z * m2.z + a2.w * m2.w;
            float s3 = a3.x * m3.x + a3.y * m3.y + a3.z * m3.z + a3.w * m3.w;
            float s4 = c0.x * o0.x + c0.y * o0.y + c0.z * o0.z + c0.w * o0.w;
            float s5 = c1.x * o1.x + c1.y * o1.y + c1.z * o1.z + c1.w * o1.w;
            float acc = ((s0 + s1) + (s2 + s3)) + (s4 + s5);

            __syncwarp();
            if (lane < 16)      sMean[w][lane] = acc;
            else if (lane < 24) sY[w][lane - 16][s] = acc;
            __syncwarp();
        }
        __syncthreads();
        for (int idx = tid; idx < 16 * 8 * ns; idx += 512) {
            int s = idx % ns;
            int bm = idx / ns;
            int m = bm & 7, bb = bm >> 3;
            out[((size_t)(bg * 16 + bb) * MM + m) * TT + cstart + t0 + s + 1] = sY[bb][m][s];
        }
    }
}

// ---------------------------------------------------------------------------
// Kernel 7: exact per-batch fallback for NaN-containing batches
// ---------------------------------------------------------------------------
__global__ void slow_kernel(const float* __restrict__ x, const float* __restrict__ F_,
                            const float* __restrict__ H_, const float* __restrict__ Q_,
                            const float* __restrict__ R_, float* __restrict__ out) {
    int b = blockIdx.x;
    if (!g_nan[b]) return;
    int tid = threadIdx.x;
    __shared__ float sF[256], sH[128], sQ[256], sR[64];
    __shared__ float cov[256], covn[256], P[128], W[2][128], K[128], CU[256], FC[256];
    __shared__ float mean[16], meanu[16], meanp[16], obs[8], resid[8];
    __shared__ int nanb;

    sF[tid] = F_[tid];
    sQ[tid] = Q_[tid];
    if (tid < 128) sH[tid] = H_[tid];
    if (tid < 64)  sR[tid] = R_[tid];
    cov[tid] = ((tid >> 4) == (tid & 15)) ? 1.f : 0.f;
    if (tid < 16) mean[tid] = 0.f;
    if (tid < 8)  out[((size_t)b * MM + tid) * TT] = 0.f;
    __syncthreads();

    for (int t = 0; t < NS; t++) {
        if (tid == 0) {
            int nb = 0;
            for (int j = 0; j < 8; j++) {
                float v = x[((size_t)b * MM + j) * TT + t];
                if (isnan(v)) { nb = 1; v = 0.f; }
                obs[j] = v;
            }
            nanb = nb;
        }
        __syncthreads();
        if (tid < 128) {
            int i = tid >> 3, j = tid & 7;
            float s = 0.f;
            #pragma unroll
            for (int e = 0; e < 16; e++) s += cov[i * 16 + e] * sH[j * 16 + e];
            P[tid] = s;
        }
        if (tid >= 128 && tid < 136) {
            int j = tid - 128;
            float s = obs[j];
            #pragma unroll
            for (int e = 0; e < 16; e++) s -= sH[j * 16 + e] * mean[e];
            resid[j] = s;
        }
        __syncthreads();
        if (tid < 128) {
            int a = tid >> 4, c = tid & 15;
            float v;
            if (c < 8) {
                float s = sR[a * 8 + c];
                #pragma unroll
                for (int e = 0; e < 16; e++) s += sH[a * 16 + e] * P[e * 8 + c];
                v = s;
            } else v = (a == (c - 8)) ? 1.f : 0.f;
            W[0][a * 16 + c] = v;
        }
        __syncthreads();
        #pragma unroll 1
        for (int k = 0; k < 8; k++) {
            int cur = k & 1;
            if (tid < 128) {
                int a = tid >> 4, c = tid & 15;
                float piv = W[cur][k * 16 + k];
                float wkc = W[cur][k * 16 + c] / piv;
                W[cur ^ 1][a * 16 + c] = (a == k) ? wkc
                                                  : W[cur][a * 16 + c] - W[cur][a * 16 + k] * wkc;
            }
            __syncthreads();
        }
        if (tid < 128) {
            int i = tid >> 3, j = tid & 7;
            float s = 0.f;
            #pragma unroll
            for (int a = 0; a < 8; a++) s += P[i * 8 + a] * W[0][a * 16 + 8 + j];
            K[tid] = s;
        }
        __syncthreads();
        if (tid < 16) {
            float s = mean[tid];
            #pragma unroll
            for (int a = 0; a < 8; a++) s += K[tid * 8 + a] * resid[a];
            meanu[tid] = nanb ? mean[tid] : s;
        }
        {
            int i = tid >> 4, j = tid & 15;
            float s = cov[tid];
            #pragma unroll
            for (int a = 0; a < 8; a++) s -= K[i * 8 + a] * P[j * 8 + a];
            CU[tid] = nanb ? cov[tid] : s;
        }
        __syncthreads();
        {
            int i = tid >> 4, j = tid & 15;
            float s = 0.f;
            #pragma unroll
            for (int e = 0; e < 16; e++)
                s += sF[i * 16 + e] * 0.5f * (CU[e * 16 + j] + CU[j * 16 + e]);
            FC[tid] = s;
        }
        if (tid < 16) {
            float s = 0.f;
            #pragma unroll
            for (int e = 0; e < 16; e++) s += sF[tid * 16 + e] * meanu[e];
            meanp[tid] = s;
        }
        __syncthreads();
        {
            int i = tid >> 4, j = tid & 15;
            float s = sQ[tid];
            #pragma unroll
            for (int e = 0; e < 16; e++) s += FC[i * 16 + e] * sF[j * 16 + e];
            covn[tid] = s;
        }
        if (tid < 8) {
            float s = 0.f;
            #pragma unroll
            for (int e = 0; e < 16; e++) s += sH[tid * 16 + e] * meanp[e];
            out[((size_t)b * MM + tid) * TT + t + 1] = s;
        }
        __syncthreads();
        cov[tid] = covn[tid];
        if (tid < 16) mean[tid] = meanp[tid];
        __syncthreads();
    }
}

// ---------------------------------------------------------------------------
extern "C" void kernel_launch(void* const* d_in, const int* in_sizes, int n_in,
                              void* d_out, int out_size) {
    const float* x = (const float*)d_in[0];
    const float* F = (const float*)d_in[1];
    const float* H = (const float*)d_in[2];
    const float* Q = (const float*)d_in[3];
    const float* R = (const float*)d_in[4];
    float* out = (float*)d_out;

    nan_scan_kernel<<<BS, 256>>>(x);
    phase1_kernel<<<1, 256>>>(F, H, Q, R);
    fill_kernel<<<NS, 256>>>();
    chunk_mats_kernel<<<NCH, 256>>>();
    bvec_kernel<<<NCH * (BS / BGB), 256>>>(x);        // 32 chunks x 64 batchgroups
    scan_kernel<<<BS / 8, 256>>>();
    phase2b_kernel<<<NCH * (BS / 16), 512>>>(x, out); // 32 chunks x 32 batchgroups
    slow_kernel<<<BS, 256>>>(x, F, H, Q, R, out);
}